// round 16
// baseline (speedup 1.0000x reference)
#include <cuda_runtime.h>
#include <cuda_bf16.h>
#include <cstdint>

#define T_STEPS 512
#define B_SZ    1024
#define D_IN    128
#define H_SZ    256
#define G3      (3 * H_SZ)   // 768

#define SC_GRID 128          // 16 b-tiles x 8 j-tiles, 1 CTA/SM, 512 thr

// ---------------------------------------------------------------------------
// Scratch (device globals)
// ---------------------------------------------------------------------------
__device__ float g_gi[(size_t)T_STEPS * B_SZ * G3];
__device__ __align__(16) unsigned char g_htile[2][16][2 * 32768];
__device__ __align__(32) unsigned g_flags[16][8];
// W_ih pre-split image: [n-block][hi/lo][64x128 bf16, gi swizzled layout]
__device__ __align__(16) unsigned char g_wih_img[12][2][16384];

// ---------------------------------------------------------------------------
// Helpers
// ---------------------------------------------------------------------------
__device__ __forceinline__ unsigned smem_u32(const void* p) {
    unsigned a;
    asm("{ .reg .u64 t; cvta.to.shared.u64 t, %1; cvt.u32.u64 %0, t; }" : "=r"(a) : "l"(p));
    return a;
}

// 512 B/row tile (256 bf16), 16B-chunk XOR swizzle (scan tiles)
__device__ __forceinline__ unsigned toff(int row, int chunk) {
    return (unsigned)row * 512u + (unsigned)((chunk ^ (row & 7)) << 4);
}
// 256 B/row variant (gi tiles, K=128)
__device__ __forceinline__ unsigned toff128(int row, int chunk) {
    return (unsigned)row * 256u + (unsigned)((chunk ^ (row & 7)) << 4);
}

__device__ __forceinline__ uint4 pack8(const unsigned s[8]) {
    return make_uint4(s[0] | (s[1] << 16), s[2] | (s[3] << 16),
                      s[4] | (s[5] << 16), s[6] | (s[7] << 16));
}

__device__ __forceinline__ void split8(const float v[8], uint4& hi, uint4& lo) {
    unsigned h[8], l[8];
#pragma unroll
    for (int i = 0; i < 8; i++) {
        __nv_bfloat16 bh = __float2bfloat16(v[i]);
        float fh = __bfloat162float(bh);
        __nv_bfloat16 bl = __float2bfloat16(v[i] - fh);
        h[i] = (unsigned)__bfloat16_as_ushort(bh);
        l[i] = (unsigned)__bfloat16_as_ushort(bl);
    }
    hi = pack8(h); lo = pack8(l);
}

__device__ __forceinline__ void split4(const float v[4], uint2& hi, uint2& lo) {
    unsigned h[4], l[4];
#pragma unroll
    for (int i = 0; i < 4; i++) {
        __nv_bfloat16 bh = __float2bfloat16(v[i]);
        float fh = __bfloat162float(bh);
        __nv_bfloat16 bl = __float2bfloat16(v[i] - fh);
        h[i] = (unsigned)__bfloat16_as_ushort(bh);
        l[i] = (unsigned)__bfloat16_as_ushort(bl);
    }
    hi = make_uint2(h[0] | (h[1] << 16), h[2] | (h[3] << 16));
    lo = make_uint2(l[0] | (l[1] << 16), l[2] | (l[3] << 16));
}

__device__ __forceinline__ void unpack2(unsigned hi, unsigned lo, float& f0, float& f1) {
    f0 = __uint_as_float(hi << 16)         + __uint_as_float(lo << 16);
    f1 = __uint_as_float(hi & 0xffff0000u) + __uint_as_float(lo & 0xffff0000u);
}

__device__ __forceinline__ float fast_sigmoid(float x) {
    return __fdividef(1.0f, 1.0f + __expf(-x));
}
__device__ __forceinline__ float fast_tanh(float x) {
    return 1.0f - 2.0f * __fdividef(1.0f, __expf(2.0f * x) + 1.0f);
}

#define LDM4(r, a)                                                             \
    asm volatile("ldmatrix.sync.aligned.m8n8.x4.shared.b16 {%0,%1,%2,%3}, [%4];" \
        : "=r"((r)[0]), "=r"((r)[1]), "=r"((r)[2]), "=r"((r)[3]) : "r"(a))

#define MMA16816(c, a, b0v, b1v)                                               \
    asm volatile("mma.sync.aligned.m16n8k16.row.col.f32.bf16.bf16.f32 "        \
        "{%0,%1,%2,%3}, {%4,%5,%6,%7}, {%8,%9}, {%0,%1,%2,%3};"                \
        : "+f"((c)[0]), "+f"((c)[1]), "+f"((c)[2]), "+f"((c)[3])               \
        : "r"((a)[0]), "r"((a)[1]), "r"((a)[2]), "r"((a)[3]), "r"(b0v), "r"(b1v))

#define CP_ASYNC16(dst, src)                                                   \
    asm volatile("cp.async.cg.shared.global [%0], [%1], 16;" :: "r"(dst), "l"(src))

#define STCS2(p, v)                                                            \
    asm volatile("st.global.cs.v2.f32 [%0], {%1, %2};"                         \
        :: "l"(p), "f"((v).x), "f"((v).y) : "memory")

#define STCS4(p, v)                                                            \
    asm volatile("st.global.cs.v4.f32 [%0], {%1, %2, %3, %4};"                 \
        :: "l"(p), "f"((v).x), "f"((v).y), "f"((v).z), "f"((v).w) : "memory")

#define LDV4_VOL(r, p)                                                         \
    asm volatile("ld.volatile.global.v4.u32 {%0,%1,%2,%3}, [%4];"              \
        : "=r"((r).x), "=r"((r).y), "=r"((r).z), "=r"((r).w) : "l"(p))

// ---------------------------------------------------------------------------
// Prep: convert W_ih once into split/swizzled images (12 CTAs, ~6us)
// ---------------------------------------------------------------------------
__global__ void __launch_bounds__(256)
prep_wih(const float* __restrict__ W_ih)
{
    const int nb = blockIdx.x;
    const int tid = threadIdx.x;
#pragma unroll
    for (int c = tid; c < 64 * 16; c += 256) {
        int r = c >> 4, ch = c & 15;
        const float* wp = W_ih + (size_t)(nb * 64 + r) * D_IN + ch * 8;
        float v[8];
        *reinterpret_cast<float4*>(v)     = *reinterpret_cast<const float4*>(wp);
        *reinterpret_cast<float4*>(v + 4) = *reinterpret_cast<const float4*>(wp + 4);
        uint4 hi, lo; split8(v, hi, lo);
        unsigned off = toff128(r, ch);
        *reinterpret_cast<uint4*>(&g_wih_img[nb][0][off]) = hi;
        *reinterpret_cast<uint4*>(&g_wih_img[nb][1][off]) = lo;
    }
}

// ---------------------------------------------------------------------------
// Kernel A: gi = x @ W_ih^T + b_ih via bf16-split mma.sync (R15 version).
//   A_hi 0 | A_lo 32768 | B_hi 65536 | B_lo 81920   (96 KB -> 2 CTA/SM)
// ---------------------------------------------------------------------------
#define GI_SAHI 0u
#define GI_SALO 32768u
#define GI_SBHI 65536u
#define GI_SBLO 81920u
#define GI_SMEM 98304

__global__ void __launch_bounds__(256, 2)
gi_mma(const float* __restrict__ x,
       const float* __restrict__ b_ih)
{
    extern __shared__ char sm[];
    const unsigned sb = smem_u32(sm);

    const int tid = threadIdx.x;
    const size_t mbase = (size_t)blockIdx.x * 128;

    // ---- prologue: issue W copy for nb=0 (hides under x staging) ----
    {
        const unsigned char* whi = g_wih_img[0][0];
        const unsigned char* wlo = g_wih_img[0][1];
#pragma unroll
        for (int c = tid; c < 1024; c += 256) {
            unsigned o = (unsigned)c * 16u;
            CP_ASYNC16(sb + GI_SBHI + o, whi + o);
            CP_ASYNC16(sb + GI_SBLO + o, wlo + o);
        }
        asm volatile("cp.async.commit_group;");
    }

    // ---- stage x tile [128 x 128] split ONCE ----
#pragma unroll
    for (int c = tid; c < 128 * 16; c += 256) {
        int r = c >> 4, ch = c & 15;
        const float* xp = x + (mbase + r) * D_IN + ch * 8;
        float v[8];
        *reinterpret_cast<float4*>(v)     = *reinterpret_cast<const float4*>(xp);
        *reinterpret_cast<float4*>(v + 4) = *reinterpret_cast<const float4*>(xp + 4);
        uint4 hi, lo; split8(v, hi, lo);
        unsigned off = toff128(r, ch);
        *reinterpret_cast<uint4*>(sm + GI_SAHI + off) = hi;
        *reinterpret_cast<uint4*>(sm + GI_SALO + off) = lo;
    }

    const int lane = tid & 31;
    const int w = tid >> 5;
    const int wm = w & 3;
    const int wn = w >> 2;
    const int ra    = (lane & 7) + ((lane & 8) ? 8 : 0);
    const int parA  = (lane >> 4) & 1;
    const int rowA0 = wm * 32 + ra;
    const int rbrel = (lane & 7) + (((lane >> 4) & 1) ? 8 : 0);
    const int parB  = (lane >> 3) & 1;
    const int rowB0 = wn * 32 + rbrel;
    const int rowB1 = rowB0 + 16;
    const int tr = lane >> 2;
    const int tc = (lane & 3) * 2;

    for (int nb = 0; nb < 12; nb++) {
        const int nbase = nb * 64;

        // ---- wait for this block's W slice (issued last iteration / prologue) ----
        asm volatile("cp.async.wait_group 0;" ::: "memory");
        __syncthreads();

        float acc[2][4][4] = {};

#pragma unroll
        for (int ks = 0; ks < 8; ks++) {
            const int kc = ks * 2;
            unsigned ah0[4], ah1[4], al0[4], al1[4];
            {
                unsigned o0 = (unsigned)rowA0 * 256u + (unsigned)(((kc + parA) ^ (rowA0 & 7)) << 4);
                unsigned o1 = (unsigned)(rowA0 + 16) * 256u + (unsigned)(((kc + parA) ^ (rowA0 & 7)) << 4);
                LDM4(ah0, sb + GI_SAHI + o0);
                LDM4(ah1, sb + GI_SAHI + o1);
                LDM4(al0, sb + GI_SALO + o0);
                LDM4(al1, sb + GI_SALO + o1);
            }
            unsigned bh0[4], bh1[4], bl0[4], bl1[4];
            {
                unsigned o0 = (unsigned)rowB0 * 256u + (unsigned)(((kc + parB) ^ (rowB0 & 7)) << 4);
                unsigned o1 = (unsigned)rowB1 * 256u + (unsigned)(((kc + parB) ^ (rowB1 & 7)) << 4);
                LDM4(bh0, sb + GI_SBHI + o0);
                LDM4(bh1, sb + GI_SBHI + o1);
                LDM4(bl0, sb + GI_SBLO + o0);
                LDM4(bl1, sb + GI_SBLO + o1);
            }
            MMA16816(acc[0][0], ah0, bh0[0], bh0[1]); MMA16816(acc[0][1], ah0, bh0[2], bh0[3]);
            MMA16816(acc[0][2], ah0, bh1[0], bh1[1]); MMA16816(acc[0][3], ah0, bh1[2], bh1[3]);
            MMA16816(acc[1][0], ah1, bh0[0], bh0[1]); MMA16816(acc[1][1], ah1, bh0[2], bh0[3]);
            MMA16816(acc[1][2], ah1, bh1[0], bh1[1]); MMA16816(acc[1][3], ah1, bh1[2], bh1[3]);
            MMA16816(acc[0][0], ah0, bl0[0], bl0[1]); MMA16816(acc[0][1], ah0, bl0[2], bl0[3]);
            MMA16816(acc[0][2], ah0, bl1[0], bl1[1]); MMA16816(acc[0][3], ah0, bl1[2], bl1[3]);
            MMA16816(acc[1][0], ah1, bl0[0], bl0[1]); MMA16816(acc[1][1], ah1, bl0[2], bl0[3]);
            MMA16816(acc[1][2], ah1, bl1[0], bl1[1]); MMA16816(acc[1][3], ah1, bl1[2], bl1[3]);
            MMA16816(acc[0][0], al0, bh0[0], bh0[1]); MMA16816(acc[0][1], al0, bh0[2], bh0[3]);
            MMA16816(acc[0][2], al0, bh1[0], bh1[1]); MMA16816(acc[0][3], al0, bh1[2], bh1[3]);
            MMA16816(acc[1][0], al1, bh0[0], bh0[1]); MMA16816(acc[1][1], al1, bh0[2], bh0[3]);
            MMA16816(acc[1][2], al1, bh1[0], bh1[1]); MMA16816(acc[1][3], al1, bh1[2], bh1[3]);
        }

        // ---- epilogue: + bias, streaming store fp32 ----
#pragma unroll
        for (int i = 0; i < 2; i++) {
#pragma unroll
            for (int jn = 0; jn < 4; jn++) {
                const int col = nbase + wn * 32 + (jn >> 1) * 16 + (jn & 1) * 8 + tc;
                float2 bias = *reinterpret_cast<const float2*>(b_ih + col);
                const size_t row0 = mbase + wm * 32 + i * 16 + tr;
                float2 v0 = make_float2(acc[i][jn][0] + bias.x, acc[i][jn][1] + bias.y);
                float2 v1 = make_float2(acc[i][jn][2] + bias.x, acc[i][jn][3] + bias.y);
                STCS2(g_gi + row0 * G3 + col, v0);
                STCS2(g_gi + (row0 + 8) * G3 + col, v1);
            }
        }
        __syncthreads();   // all reads of W buffer done -> safe to overwrite

        // ---- issue next W slice copy (completes under next MMA wait) ----
        if (nb + 1 < 12) {
            const unsigned char* whi = g_wih_img[nb + 1][0];
            const unsigned char* wlo = g_wih_img[nb + 1][1];
#pragma unroll
            for (int c = tid; c < 1024; c += 256) {
                unsigned o = (unsigned)c * 16u;
                CP_ASYNC16(sb + GI_SBHI + o, whi + o);
                CP_ASYNC16(sb + GI_SBLO + o, wlo + o);
            }
            asm volatile("cp.async.commit_group;");
        }
    }
}

// ---------------------------------------------------------------------------
// Persistent GRU scan + fused LayerNorm (R12 structure; y/final-h stores
// now streaming st.cs to keep L2 for the exchange tiles + gi stream).
// ---------------------------------------------------------------------------
#define S_BIAS 0u
#define S_GH0  512u
#define S_GH1  27136u
#define S_AHI  53760u
#define S_ALO  86528u
#define S_WHI  119296u
#define S_WLO  168448u
#define S_LNW  217600u
#define S_LNB  218624u
#define SMEM_SCAN 219648
#define GH_STR 104
#define GH_HALF 6656   // floats between gh0 and gh1

__global__ void __launch_bounds__(512, 1)
gru_scan_mma(const float* __restrict__ h0,
             const float* __restrict__ masks,
             const float* __restrict__ W_hh,
             const float* __restrict__ b_hh,
             const float* __restrict__ ln_w,
             const float* __restrict__ ln_b,
             float* __restrict__ out)
{
    extern __shared__ char smem[];
    const unsigned sbase = smem_u32(smem);
    float* sbias = reinterpret_cast<float*>(smem + S_BIAS);
    float* sgh   = reinterpret_cast<float*>(smem + S_GH0);
    float* slnw  = reinterpret_cast<float*>(smem + S_LNW);
    float* slnb  = reinterpret_cast<float*>(smem + S_LNB);

    const int tid = threadIdx.x;
    const int bi = blockIdx.x >> 3;   // group 0..15
    const int ji = blockIdx.x & 7;
    const int b0 = bi * 64;
    const int j0 = ji * 32;

    unsigned bar_base;
    {
        const unsigned* fp = &g_flags[bi][ji];
        asm volatile("ld.volatile.global.u32 %0, [%1];" : "=r"(bar_base) : "l"(fp));
    }

    // ---- stage W_hh slice split to bf16 ----
    for (int c = tid; c < 96 * 32; c += 512) {
        int r  = c >> 5;
        int ch = c & 31;
        int grow = (r >> 5) * H_SZ + j0 + (r & 31);
        float v[8];
        *reinterpret_cast<float4*>(v)     = *reinterpret_cast<const float4*>(W_hh + (size_t)grow * H_SZ + ch * 8);
        *reinterpret_cast<float4*>(v + 4) = *reinterpret_cast<const float4*>(W_hh + (size_t)grow * H_SZ + ch * 8 + 4);
        uint4 hi, lo;
        split8(v, hi, lo);
        unsigned off = toff(r, ch);
        *reinterpret_cast<uint4*>(smem + S_WHI + off) = hi;
        *reinterpret_cast<uint4*>(smem + S_WLO + off) = lo;
    }
    if (tid < 96) sbias[tid] = b_hh[(tid >> 5) * H_SZ + j0 + (tid & 31)];
    if (tid < 256) { slnw[tid] = ln_w[tid]; slnb[tid] = ln_b[tid]; }

    // ---- MMA mapping (16 warps: 4 m x 2 n x 2 k-half) ----
    const int lane = tid & 31;
    const int w = tid >> 5;
    const int wm = w & 3;
    const int wn = (w >> 2) & 1;
    const int kh = w >> 3;
    const int rowA = wm * 16 + (lane & 7) + ((lane & 8) ? 8 : 0);
    const int parA = (lane >> 4) & 1;
    const int rbrel = (lane & 7) + (((lane >> 4) & 1) ? 8 : 0);
    const int parB = (lane >> 3) & 1;
    int rowB[3];
#pragma unroll
    for (int p = 0; p < 3; p++) rowB[p] = wn * 48 + p * 16 + rbrel;
    float* sghk = sgh + kh * GH_HALF;

    // ---- gate mapping: thread handles (row gr, 4 j) ----
    const int gr = tid >> 3;
    const int gq = tid & 7;
    const int jj0 = gq * 4;
    const int b = b0 + gr;
    const int jg = j0 + jj0;
    const unsigned hpo = toff(gr, jg >> 3) + (unsigned)((jg & 7) << 1);

    // ---- fused-LN mapping: warps 0-7 each own one of this CTA's 8 rows ----
    const int lrow = ji * 8 + w;
    const unsigned lnoff = toff(lrow, lane);
    float lnw8[8], lnb8[8];

    __syncthreads();
    if (w < 8) {
        *reinterpret_cast<float4*>(lnw8)     = *reinterpret_cast<const float4*>(&slnw[lane * 8]);
        *reinterpret_cast<float4*>(lnw8 + 4) = *reinterpret_cast<const float4*>(&slnw[lane * 8 + 4]);
        *reinterpret_cast<float4*>(lnb8)     = *reinterpret_cast<const float4*>(&slnb[lane * 8]);
        *reinterpret_cast<float4*>(lnb8 + 4) = *reinterpret_cast<const float4*>(&slnb[lane * 8 + 4]);
    }

    for (int t = 0; t < T_STEPS; t++) {
        // ---- stage h tile (unmasked, pre-split, pre-swizzled) ----
        if (t == 0) {
            for (int c = tid; c < 64 * 32; c += 512) {
                int r = c >> 5, ch = c & 31;
                const float* hp = h0 + (size_t)(b0 + r) * H_SZ + ch * 8;
                float v[8];
                *reinterpret_cast<float4*>(v)     = *reinterpret_cast<const float4*>(hp);
                *reinterpret_cast<float4*>(v + 4) = *reinterpret_cast<const float4*>(hp + 4);
                uint4 hi, lo;
                split8(v, hi, lo);
                unsigned off = toff(r, ch);
                *reinterpret_cast<uint4*>(smem + S_AHI + off) = hi;
                *reinterpret_cast<uint4*>(smem + S_ALO + off) = lo;
            }
        } else {
            const unsigned char* src = g_htile[(t - 1) & 1][bi];
#pragma unroll
            for (int c = tid; c < 4096; c += 512) {
                CP_ASYNC16(sbase + S_AHI + (unsigned)c * 16u, src + (size_t)c * 16);
            }
            asm volatile("cp.async.commit_group;");
        }

        // ---- gi + mask prefetch ----
        float gir[4], giz[4], gin[4];
        {
            const float* gib = g_gi + ((size_t)t * B_SZ + b) * G3 + jg;
            *reinterpret_cast<float4*>(gir) = __ldcs(reinterpret_cast<const float4*>(gib));
            *reinterpret_cast<float4*>(giz) = __ldcs(reinterpret_cast<const float4*>(gib + H_SZ));
            *reinterpret_cast<float4*>(gin) = __ldcs(reinterpret_cast<const float4*>(gib + 2 * H_SZ));
        }
        const float m = __ldg(masks + (size_t)t * B_SZ + b);

        if (t != 0) {
            asm volatile("cp.async.wait_group 0;" ::: "memory");
        }
        __syncthreads();

        // ---- tensor GEMM: this warp does 8 k-steps of its k-half ----
        float acc[6][4] = {};
#pragma unroll
        for (int ks = 0; ks < 8; ks++) {
            const int kc = (kh * 8 + ks) * 2;
            unsigned ahi[4], alo[4];
            unsigned aoffs = (unsigned)rowA * 512u + (unsigned)(((kc + parA) ^ (rowA & 7)) << 4);
            LDM4(ahi, sbase + S_AHI + aoffs);
            LDM4(alo, sbase + S_ALO + aoffs);
#pragma unroll
            for (int p = 0; p < 3; p++) {
                unsigned boffs = (unsigned)rowB[p] * 512u + (unsigned)(((kc + parB) ^ (rowB[p] & 7)) << 4);
                unsigned bh[4], bl[4];
                LDM4(bh, sbase + S_WHI + boffs);
                LDM4(bl, sbase + S_WLO + boffs);
                MMA16816(acc[2 * p],     ahi, bh[0], bh[1]);
                MMA16816(acc[2 * p + 1], ahi, bh[2], bh[3]);
                MMA16816(acc[2 * p],     ahi, bl[0], bl[1]);
                MMA16816(acc[2 * p + 1], ahi, bl[2], bl[3]);
                MMA16816(acc[2 * p],     alo, bh[0], bh[1]);
                MMA16816(acc[2 * p + 1], alo, bh[2], bh[3]);
            }
        }

        // ---- accumulators -> smem partials ----
        {
            const int r0 = wm * 16 + lane / 4;
            const int cb = wn * 48 + (lane % 4) * 2;
#pragma unroll
            for (int i = 0; i < 6; i++) {
                const int col = cb + (i >> 1) * 16 + (i & 1) * 8;
                *reinterpret_cast<float2*>(&sghk[r0 * GH_STR + col])       = make_float2(acc[i][0], acc[i][1]);
                *reinterpret_cast<float2*>(&sghk[(r0 + 8) * GH_STR + col]) = make_float2(acc[i][2], acc[i][3]);
            }
        }
        __syncthreads();

        // ---- gates (mask folded: gh_masked = m*gh_raw, hp = m*h_raw) ----
        {
            float4 r0 = *reinterpret_cast<const float4*>(&sgh[gr * GH_STR + jj0]);
            float4 r1 = *reinterpret_cast<const float4*>(&sgh[GH_HALF + gr * GH_STR + jj0]);
            float4 z0 = *reinterpret_cast<const float4*>(&sgh[gr * GH_STR + 32 + jj0]);
            float4 z1 = *reinterpret_cast<const float4*>(&sgh[GH_HALF + gr * GH_STR + 32 + jj0]);
            float4 n0 = *reinterpret_cast<const float4*>(&sgh[gr * GH_STR + 64 + jj0]);
            float4 n1 = *reinterpret_cast<const float4*>(&sgh[GH_HALF + gr * GH_STR + 64 + jj0]);
            float ghr[4] = {r0.x + r1.x, r0.y + r1.y, r0.z + r1.z, r0.w + r1.w};
            float ghz[4] = {z0.x + z1.x, z0.y + z1.y, z0.z + z1.z, z0.w + z1.w};
            float ghn[4] = {n0.x + n1.x, n0.y + n1.y, n0.z + n1.z, n0.w + n1.w};

            float hpv[4];
            {
                uint2 hi = *reinterpret_cast<const uint2*>(smem + S_AHI + hpo);
                uint2 lo = *reinterpret_cast<const uint2*>(smem + S_ALO + hpo);
                unpack2(hi.x, lo.x, hpv[0], hpv[1]);
                unpack2(hi.y, lo.y, hpv[2], hpv[3]);
            }

            float hv[4];
#pragma unroll
            for (int i = 0; i < 4; i++) {
                float br = sbias[jj0 + i];
                float bz = sbias[32 + jj0 + i];
                float bn = sbias[64 + jj0 + i];
                float r = fast_sigmoid(gir[i] + m * ghr[i] + br);
                float z = fast_sigmoid(giz[i] + m * ghz[i] + bz);
                float n = fast_tanh(gin[i] + r * (m * ghn[i] + bn));
                hv[i] = (1.0f - z) * n + z * (m * hpv[i]);
            }

            // h exchange write: split, already-swizzled tile image
            uint2 oh, ol;
            split4(hv, oh, ol);
            unsigned char* dst = g_htile[t & 1][bi];
            *reinterpret_cast<uint2*>(dst + hpo)         = oh;
            *reinterpret_cast<uint2*>(dst + 32768 + hpo) = ol;

            if (t == T_STEPS - 1) {
                float* fp = out + (size_t)T_STEPS * B_SZ * H_SZ + (size_t)b * H_SZ + jg;
                float4 fv = make_float4(hv[0], hv[1], hv[2], hv[3]);
                STCS4(fp, fv);
            }
        }

        // ---- release this CTA's flag as soon as h writes are visible ----
        __syncthreads();
        const unsigned target = bar_base + (unsigned)t + 1u;
        if (tid == 0) {
            asm volatile("st.release.gpu.global.u32 [%0], %1;"
                         :: "l"(&g_flags[bi][ji]), "r"(target) : "memory");
        }

        // ---- fused LN of y(t-1) = A tile rows (hides peer skew) ----
        if (t > 0 && w < 8) {
            uint4 hi = *reinterpret_cast<const uint4*>(smem + S_AHI + lnoff);
            uint4 lo = *reinterpret_cast<const uint4*>(smem + S_ALO + lnoff);
            float v[8];
            unpack2(hi.x, lo.x, v[0], v[1]);
            unpack2(hi.y, lo.y, v[2], v[3]);
            unpack2(hi.z, lo.z, v[4], v[5]);
            unpack2(hi.w, lo.w, v[6], v[7]);
            float s = v[0] + v[1] + v[2] + v[3] + v[4] + v[5] + v[6] + v[7];
#pragma unroll
            for (int o = 16; o; o >>= 1) s += __shfl_xor_sync(0xffffffffu, s, o);
            const float mu = s * (1.0f / 256.0f);
            float q = 0.f;
#pragma unroll
            for (int i = 0; i < 8; i++) { float d = v[i] - mu; q += d * d; }
#pragma unroll
            for (int o = 16; o; o >>= 1) q += __shfl_xor_sync(0xffffffffu, q, o);
            const float rs = rsqrtf(q * (1.0f / 256.0f) + 1e-5f);
            float o8[8];
#pragma unroll
            for (int i = 0; i < 8; i++) o8[i] = (v[i] - mu) * rs * lnw8[i] + lnb8[i];
            float* yp = out + ((size_t)(t - 1) * B_SZ + b0 + lrow) * H_SZ + lane * 8;
            STCS4(yp,     *reinterpret_cast<float4*>(o8));
            STCS4(yp + 4, *reinterpret_cast<float4*>(o8 + 4));
        }

        // ---- poll all 8 group flags ----
        if (tid == 0) {
            const unsigned* fb = &g_flags[bi][0];
            uint4 f0, f1;
            for (;;) {
                LDV4_VOL(f0, fb);
                LDV4_VOL(f1, fb + 4);
                if (f0.x == target && f0.y == target && f0.z == target && f0.w == target &&
                    f1.x == target && f1.y == target && f1.z == target && f1.w == target)
                    break;
            }
            asm volatile("fence.acq_rel.gpu;" ::: "memory");
        }
        __syncthreads();
    }

    // ---- epilogue: LN of y(T-1) from the final h tile ----
    {
        const unsigned char* src = g_htile[(T_STEPS - 1) & 1][bi];
#pragma unroll
        for (int c = tid; c < 4096; c += 512) {
            CP_ASYNC16(sbase + S_AHI + (unsigned)c * 16u, src + (size_t)c * 16);
        }
        asm volatile("cp.async.commit_group;");
        asm volatile("cp.async.wait_group 0;" ::: "memory");
        __syncthreads();

        if (w < 8) {
            uint4 hi = *reinterpret_cast<const uint4*>(smem + S_AHI + lnoff);
            uint4 lo = *reinterpret_cast<const uint4*>(smem + S_ALO + lnoff);
            float v[8];
            unpack2(hi.x, lo.x, v[0], v[1]);
            unpack2(hi.y, lo.y, v[2], v[3]);
            unpack2(hi.z, lo.z, v[4], v[5]);
            unpack2(hi.w, lo.w, v[6], v[7]);
            float s = v[0] + v[1] + v[2] + v[3] + v[4] + v[5] + v[6] + v[7];
#pragma unroll
            for (int o = 16; o; o >>= 1) s += __shfl_xor_sync(0xffffffffu, s, o);
            const float mu = s * (1.0f / 256.0f);
            float q = 0.f;
#pragma unroll
            for (int i = 0; i < 8; i++) { float d = v[i] - mu; q += d * d; }
#pragma unroll
            for (int o = 16; o; o >>= 1) q += __shfl_xor_sync(0xffffffffu, q, o);
            const float rs = rsqrtf(q * (1.0f / 256.0f) + 1e-5f);
            float o8[8];
#pragma unroll
            for (int i = 0; i < 8; i++) o8[i] = (v[i] - mu) * rs * lnw8[i] + lnb8[i];
            float* yp = out + ((size_t)(T_STEPS - 1) * B_SZ + b0 + lrow) * H_SZ + lane * 8;
            STCS4(yp,     *reinterpret_cast<float4*>(o8));
            STCS4(yp + 4, *reinterpret_cast<float4*>(o8 + 4));
        }
    }
}

// ---------------------------------------------------------------------------
extern "C" void kernel_launch(void* const* d_in, const int* in_sizes, int n_in,
                              void* d_out, int out_size)
{
    const float* x     = (const float*)d_in[0];
    const float* h0    = (const float*)d_in[1];
    const float* masks = (const float*)d_in[2];
    const float* W_ih  = (const float*)d_in[3];
    const float* W_hh  = (const float*)d_in[4];
    const float* b_ih  = (const float*)d_in[5];
    const float* b_hh  = (const float*)d_in[6];
    const float* ln_w  = (const float*)d_in[7];
    const float* ln_b  = (const float*)d_in[8];
    float* out = (float*)d_out;

    (void)in_sizes; (void)n_in; (void)out_size;

    cudaFuncSetAttribute(gi_mma, cudaFuncAttributeMaxDynamicSharedMemorySize, GI_SMEM);
    cudaFuncSetAttribute(gru_scan_mma, cudaFuncAttributeMaxDynamicSharedMemorySize, SMEM_SCAN);

    prep_wih<<<12, 256>>>(W_ih);

    gi_mma<<<(T_STEPS * B_SZ) / 128, 256, GI_SMEM>>>(x, b_ih);

    gru_scan_mma<<<SC_GRID, 512, SMEM_SCAN>>>(h0, masks, W_hh, b_hh, ln_w, ln_b, out);
}

// round 17
// speedup vs baseline: 1.0026x; 1.0026x over previous
#include <cuda_runtime.h>
#include <cuda_bf16.h>
#include <cstdint>

#define T_STEPS 512
#define B_SZ    1024
#define D_IN    128
#define H_SZ    256
#define G3      (3 * H_SZ)   // 768

#define SC_GRID 128          // 16 b-tiles x 8 j-tiles, 1 CTA/SM, 512 thr

// ---------------------------------------------------------------------------
// Scratch (device globals)
// ---------------------------------------------------------------------------
__device__ float g_gi[(size_t)T_STEPS * B_SZ * G3];
__device__ __align__(16) unsigned char g_htile[2][16][2 * 32768];
__device__ __align__(32) unsigned g_flags[16][8];
// W_ih pre-split image: [n-block][hi/lo][64x128 bf16, gi swizzled layout]
__device__ __align__(16) unsigned char g_wih_img[12][2][16384];

// ---------------------------------------------------------------------------
// Helpers
// ---------------------------------------------------------------------------
__device__ __forceinline__ unsigned smem_u32(const void* p) {
    unsigned a;
    asm("{ .reg .u64 t; cvta.to.shared.u64 t, %1; cvt.u32.u64 %0, t; }" : "=r"(a) : "l"(p));
    return a;
}

// 512 B/row tile (256 bf16), 16B-chunk XOR swizzle (scan tiles)
__device__ __forceinline__ unsigned toff(int row, int chunk) {
    return (unsigned)row * 512u + (unsigned)((chunk ^ (row & 7)) << 4);
}
// 256 B/row variant (gi tiles, K=128)
__device__ __forceinline__ unsigned toff128(int row, int chunk) {
    return (unsigned)row * 256u + (unsigned)((chunk ^ (row & 7)) << 4);
}

__device__ __forceinline__ uint4 pack8(const unsigned s[8]) {
    return make_uint4(s[0] | (s[1] << 16), s[2] | (s[3] << 16),
                      s[4] | (s[5] << 16), s[6] | (s[7] << 16));
}

__device__ __forceinline__ void split8(const float v[8], uint4& hi, uint4& lo) {
    unsigned h[8], l[8];
#pragma unroll
    for (int i = 0; i < 8; i++) {
        __nv_bfloat16 bh = __float2bfloat16(v[i]);
        float fh = __bfloat162float(bh);
        __nv_bfloat16 bl = __float2bfloat16(v[i] - fh);
        h[i] = (unsigned)__bfloat16_as_ushort(bh);
        l[i] = (unsigned)__bfloat16_as_ushort(bl);
    }
    hi = pack8(h); lo = pack8(l);
}

__device__ __forceinline__ void split4(const float v[4], uint2& hi, uint2& lo) {
    unsigned h[4], l[4];
#pragma unroll
    for (int i = 0; i < 4; i++) {
        __nv_bfloat16 bh = __float2bfloat16(v[i]);
        float fh = __bfloat162float(bh);
        __nv_bfloat16 bl = __float2bfloat16(v[i] - fh);
        h[i] = (unsigned)__bfloat16_as_ushort(bh);
        l[i] = (unsigned)__bfloat16_as_ushort(bl);
    }
    hi = make_uint2(h[0] | (h[1] << 16), h[2] | (h[3] << 16));
    lo = make_uint2(l[0] | (l[1] << 16), l[2] | (l[3] << 16));
}

__device__ __forceinline__ void unpack2(unsigned hi, unsigned lo, float& f0, float& f1) {
    f0 = __uint_as_float(hi << 16)         + __uint_as_float(lo << 16);
    f1 = __uint_as_float(hi & 0xffff0000u) + __uint_as_float(lo & 0xffff0000u);
}

__device__ __forceinline__ float fast_sigmoid(float x) {
    return __fdividef(1.0f, 1.0f + __expf(-x));
}
__device__ __forceinline__ float fast_tanh(float x) {
    return 1.0f - 2.0f * __fdividef(1.0f, __expf(2.0f * x) + 1.0f);
}

#define LDM4(r, a)                                                             \
    asm volatile("ldmatrix.sync.aligned.m8n8.x4.shared.b16 {%0,%1,%2,%3}, [%4];" \
        : "=r"((r)[0]), "=r"((r)[1]), "=r"((r)[2]), "=r"((r)[3]) : "r"(a))

#define MMA16816(c, a, b0v, b1v)                                               \
    asm volatile("mma.sync.aligned.m16n8k16.row.col.f32.bf16.bf16.f32 "        \
        "{%0,%1,%2,%3}, {%4,%5,%6,%7}, {%8,%9}, {%0,%1,%2,%3};"                \
        : "+f"((c)[0]), "+f"((c)[1]), "+f"((c)[2]), "+f"((c)[3])               \
        : "r"((a)[0]), "r"((a)[1]), "r"((a)[2]), "r"((a)[3]), "r"(b0v), "r"(b1v))

#define CP_ASYNC16(dst, src)                                                   \
    asm volatile("cp.async.cg.shared.global [%0], [%1], 16;" :: "r"(dst), "l"(src))

#define STCS2(p, v)                                                            \
    asm volatile("st.global.cs.v2.f32 [%0], {%1, %2};"                         \
        :: "l"(p), "f"((v).x), "f"((v).y) : "memory")

#define LDV4_VOL(r, p)                                                         \
    asm volatile("ld.volatile.global.v4.u32 {%0,%1,%2,%3}, [%4];"              \
        : "=r"((r).x), "=r"((r).y), "=r"((r).z), "=r"((r).w) : "l"(p))

// ---------------------------------------------------------------------------
// Prep: convert W_ih once into split/swizzled images (48 CTAs, ~3us)
// ---------------------------------------------------------------------------
__global__ void __launch_bounds__(256)
prep_wih(const float* __restrict__ W_ih)
{
    const int nb = blockIdx.x >> 2;          // 0..11
    const int part = blockIdx.x & 3;         // 0..3
    const int tid = threadIdx.x;
    const int c = part * 256 + tid;          // 0..1023 (one 8-elem group each)
    {
        int r = c >> 4, ch = c & 15;
        const float* wp = W_ih + (size_t)(nb * 64 + r) * D_IN + ch * 8;
        float v[8];
        *reinterpret_cast<float4*>(v)     = *reinterpret_cast<const float4*>(wp);
        *reinterpret_cast<float4*>(v + 4) = *reinterpret_cast<const float4*>(wp + 4);
        uint4 hi, lo; split8(v, hi, lo);
        unsigned off = toff128(r, ch);
        *reinterpret_cast<uint4*>(&g_wih_img[nb][0][off]) = hi;
        *reinterpret_cast<uint4*>(&g_wih_img[nb][1][off]) = lo;
    }
}

// ---------------------------------------------------------------------------
// Kernel A: gi = x @ W_ih^T + b_ih via bf16-split mma.sync (R15 version).
//   A_hi 0 | A_lo 32768 | B_hi 65536 | B_lo 81920   (96 KB -> 2 CTA/SM)
// ---------------------------------------------------------------------------
#define GI_SAHI 0u
#define GI_SALO 32768u
#define GI_SBHI 65536u
#define GI_SBLO 81920u
#define GI_SMEM 98304

__global__ void __launch_bounds__(256, 2)
gi_mma(const float* __restrict__ x,
       const float* __restrict__ b_ih)
{
    extern __shared__ char sm[];
    const unsigned sb = smem_u32(sm);

    const int tid = threadIdx.x;
    const size_t mbase = (size_t)blockIdx.x * 128;

    // ---- prologue: issue W copy for nb=0 (hides under x staging) ----
    {
        const unsigned char* whi = g_wih_img[0][0];
        const unsigned char* wlo = g_wih_img[0][1];
#pragma unroll
        for (int c = tid; c < 1024; c += 256) {
            unsigned o = (unsigned)c * 16u;
            CP_ASYNC16(sb + GI_SBHI + o, whi + o);
            CP_ASYNC16(sb + GI_SBLO + o, wlo + o);
        }
        asm volatile("cp.async.commit_group;");
    }

    // ---- stage x tile [128 x 128] split ONCE ----
#pragma unroll
    for (int c = tid; c < 128 * 16; c += 256) {
        int r = c >> 4, ch = c & 15;
        const float* xp = x + (mbase + r) * D_IN + ch * 8;
        float v[8];
        *reinterpret_cast<float4*>(v)     = *reinterpret_cast<const float4*>(xp);
        *reinterpret_cast<float4*>(v + 4) = *reinterpret_cast<const float4*>(xp + 4);
        uint4 hi, lo; split8(v, hi, lo);
        unsigned off = toff128(r, ch);
        *reinterpret_cast<uint4*>(sm + GI_SAHI + off) = hi;
        *reinterpret_cast<uint4*>(sm + GI_SALO + off) = lo;
    }

    const int lane = tid & 31;
    const int w = tid >> 5;
    const int wm = w & 3;
    const int wn = w >> 2;
    const int ra    = (lane & 7) + ((lane & 8) ? 8 : 0);
    const int parA  = (lane >> 4) & 1;
    const int rowA0 = wm * 32 + ra;
    const int rbrel = (lane & 7) + (((lane >> 4) & 1) ? 8 : 0);
    const int parB  = (lane >> 3) & 1;
    const int rowB0 = wn * 32 + rbrel;
    const int rowB1 = rowB0 + 16;
    const int tr = lane >> 2;
    const int tc = (lane & 3) * 2;

    for (int nb = 0; nb < 12; nb++) {
        const int nbase = nb * 64;

        // ---- wait for this block's W slice (issued last iteration / prologue) ----
        asm volatile("cp.async.wait_group 0;" ::: "memory");
        __syncthreads();

        float acc[2][4][4] = {};

#pragma unroll
        for (int ks = 0; ks < 8; ks++) {
            const int kc = ks * 2;
            unsigned ah0[4], ah1[4], al0[4], al1[4];
            {
                unsigned o0 = (unsigned)rowA0 * 256u + (unsigned)(((kc + parA) ^ (rowA0 & 7)) << 4);
                unsigned o1 = (unsigned)(rowA0 + 16) * 256u + (unsigned)(((kc + parA) ^ (rowA0 & 7)) << 4);
                LDM4(ah0, sb + GI_SAHI + o0);
                LDM4(ah1, sb + GI_SAHI + o1);
                LDM4(al0, sb + GI_SALO + o0);
                LDM4(al1, sb + GI_SALO + o1);
            }
            unsigned bh0[4], bh1[4], bl0[4], bl1[4];
            {
                unsigned o0 = (unsigned)rowB0 * 256u + (unsigned)(((kc + parB) ^ (rowB0 & 7)) << 4);
                unsigned o1 = (unsigned)rowB1 * 256u + (unsigned)(((kc + parB) ^ (rowB1 & 7)) << 4);
                LDM4(bh0, sb + GI_SBHI + o0);
                LDM4(bh1, sb + GI_SBHI + o1);
                LDM4(bl0, sb + GI_SBLO + o0);
                LDM4(bl1, sb + GI_SBLO + o1);
            }
            MMA16816(acc[0][0], ah0, bh0[0], bh0[1]); MMA16816(acc[0][1], ah0, bh0[2], bh0[3]);
            MMA16816(acc[0][2], ah0, bh1[0], bh1[1]); MMA16816(acc[0][3], ah0, bh1[2], bh1[3]);
            MMA16816(acc[1][0], ah1, bh0[0], bh0[1]); MMA16816(acc[1][1], ah1, bh0[2], bh0[3]);
            MMA16816(acc[1][2], ah1, bh1[0], bh1[1]); MMA16816(acc[1][3], ah1, bh1[2], bh1[3]);
            MMA16816(acc[0][0], ah0, bl0[0], bl0[1]); MMA16816(acc[0][1], ah0, bl0[2], bl0[3]);
            MMA16816(acc[0][2], ah0, bl1[0], bl1[1]); MMA16816(acc[0][3], ah0, bl1[2], bl1[3]);
            MMA16816(acc[1][0], ah1, bl0[0], bl0[1]); MMA16816(acc[1][1], ah1, bl0[2], bl0[3]);
            MMA16816(acc[1][2], ah1, bl1[0], bl1[1]); MMA16816(acc[1][3], ah1, bl1[2], bl1[3]);
            MMA16816(acc[0][0], al0, bh0[0], bh0[1]); MMA16816(acc[0][1], al0, bh0[2], bh0[3]);
            MMA16816(acc[0][2], al0, bh1[0], bh1[1]); MMA16816(acc[0][3], al0, bh1[2], bh1[3]);
            MMA16816(acc[1][0], al1, bh0[0], bh0[1]); MMA16816(acc[1][1], al1, bh0[2], bh0[3]);
            MMA16816(acc[1][2], al1, bh1[0], bh1[1]); MMA16816(acc[1][3], al1, bh1[2], bh1[3]);
        }

        // ---- epilogue: + bias, streaming store fp32 ----
#pragma unroll
        for (int i = 0; i < 2; i++) {
#pragma unroll
            for (int jn = 0; jn < 4; jn++) {
                const int col = nbase + wn * 32 + (jn >> 1) * 16 + (jn & 1) * 8 + tc;
                float2 bias = *reinterpret_cast<const float2*>(b_ih + col);
                const size_t row0 = mbase + wm * 32 + i * 16 + tr;
                float2 v0 = make_float2(acc[i][jn][0] + bias.x, acc[i][jn][1] + bias.y);
                float2 v1 = make_float2(acc[i][jn][2] + bias.x, acc[i][jn][3] + bias.y);
                STCS2(g_gi + row0 * G3 + col, v0);
                STCS2(g_gi + (row0 + 8) * G3 + col, v1);
            }
        }
        __syncthreads();   // all reads of W buffer done -> safe to overwrite

        // ---- issue next W slice copy (completes under next MMA wait) ----
        if (nb + 1 < 12) {
            const unsigned char* whi = g_wih_img[nb + 1][0];
            const unsigned char* wlo = g_wih_img[nb + 1][1];
#pragma unroll
            for (int c = tid; c < 1024; c += 256) {
                unsigned o = (unsigned)c * 16u;
                CP_ASYNC16(sb + GI_SBHI + o, whi + o);
                CP_ASYNC16(sb + GI_SBLO + o, wlo + o);
            }
            asm volatile("cp.async.commit_group;");
        }
    }
}

// ---------------------------------------------------------------------------
// Persistent GRU scan + fused LayerNorm (R12/R15 version, verbatim).
// ---------------------------------------------------------------------------
#define S_BIAS 0u
#define S_GH0  512u
#define S_GH1  27136u
#define S_AHI  53760u
#define S_ALO  86528u
#define S_WHI  119296u
#define S_WLO  168448u
#define S_LNW  217600u
#define S_LNB  218624u
#define SMEM_SCAN 219648
#define GH_STR 104
#define GH_HALF 6656   // floats between gh0 and gh1

__global__ void __launch_bounds__(512, 1)
gru_scan_mma(const float* __restrict__ h0,
             const float* __restrict__ masks,
             const float* __restrict__ W_hh,
             const float* __restrict__ b_hh,
             const float* __restrict__ ln_w,
             const float* __restrict__ ln_b,
             float* __restrict__ out)
{
    extern __shared__ char smem[];
    const unsigned sbase = smem_u32(smem);
    float* sbias = reinterpret_cast<float*>(smem + S_BIAS);
    float* sgh   = reinterpret_cast<float*>(smem + S_GH0);
    float* slnw  = reinterpret_cast<float*>(smem + S_LNW);
    float* slnb  = reinterpret_cast<float*>(smem + S_LNB);

    const int tid = threadIdx.x;
    const int bi = blockIdx.x >> 3;   // group 0..15
    const int ji = blockIdx.x & 7;
    const int b0 = bi * 64;
    const int j0 = ji * 32;

    unsigned bar_base;
    {
        const unsigned* fp = &g_flags[bi][ji];
        asm volatile("ld.volatile.global.u32 %0, [%1];" : "=r"(bar_base) : "l"(fp));
    }

    // ---- stage W_hh slice split to bf16 ----
    for (int c = tid; c < 96 * 32; c += 512) {
        int r  = c >> 5;
        int ch = c & 31;
        int grow = (r >> 5) * H_SZ + j0 + (r & 31);
        float v[8];
        *reinterpret_cast<float4*>(v)     = *reinterpret_cast<const float4*>(W_hh + (size_t)grow * H_SZ + ch * 8);
        *reinterpret_cast<float4*>(v + 4) = *reinterpret_cast<const float4*>(W_hh + (size_t)grow * H_SZ + ch * 8 + 4);
        uint4 hi, lo;
        split8(v, hi, lo);
        unsigned off = toff(r, ch);
        *reinterpret_cast<uint4*>(smem + S_WHI + off) = hi;
        *reinterpret_cast<uint4*>(smem + S_WLO + off) = lo;
    }
    if (tid < 96) sbias[tid] = b_hh[(tid >> 5) * H_SZ + j0 + (tid & 31)];
    if (tid < 256) { slnw[tid] = ln_w[tid]; slnb[tid] = ln_b[tid]; }

    // ---- MMA mapping (16 warps: 4 m x 2 n x 2 k-half) ----
    const int lane = tid & 31;
    const int w = tid >> 5;
    const int wm = w & 3;
    const int wn = (w >> 2) & 1;
    const int kh = w >> 3;
    const int rowA = wm * 16 + (lane & 7) + ((lane & 8) ? 8 : 0);
    const int parA = (lane >> 4) & 1;
    const int rbrel = (lane & 7) + (((lane >> 4) & 1) ? 8 : 0);
    const int parB = (lane >> 3) & 1;
    int rowB[3];
#pragma unroll
    for (int p = 0; p < 3; p++) rowB[p] = wn * 48 + p * 16 + rbrel;
    float* sghk = sgh + kh * GH_HALF;

    // ---- gate mapping: thread handles (row gr, 4 j) ----
    const int gr = tid >> 3;
    const int gq = tid & 7;
    const int jj0 = gq * 4;
    const int b = b0 + gr;
    const int jg = j0 + jj0;
    const unsigned hpo = toff(gr, jg >> 3) + (unsigned)((jg & 7) << 1);

    // ---- fused-LN mapping: warps 0-7 each own one of this CTA's 8 rows ----
    const int lrow = ji * 8 + w;
    const unsigned lnoff = toff(lrow, lane);
    float lnw8[8], lnb8[8];

    __syncthreads();
    if (w < 8) {
        *reinterpret_cast<float4*>(lnw8)     = *reinterpret_cast<const float4*>(&slnw[lane * 8]);
        *reinterpret_cast<float4*>(lnw8 + 4) = *reinterpret_cast<const float4*>(&slnw[lane * 8 + 4]);
        *reinterpret_cast<float4*>(lnb8)     = *reinterpret_cast<const float4*>(&slnb[lane * 8]);
        *reinterpret_cast<float4*>(lnb8 + 4) = *reinterpret_cast<const float4*>(&slnb[lane * 8 + 4]);
    }

    for (int t = 0; t < T_STEPS; t++) {
        // ---- stage h tile (unmasked, pre-split, pre-swizzled) ----
        if (t == 0) {
            for (int c = tid; c < 64 * 32; c += 512) {
                int r = c >> 5, ch = c & 31;
                const float* hp = h0 + (size_t)(b0 + r) * H_SZ + ch * 8;
                float v[8];
                *reinterpret_cast<float4*>(v)     = *reinterpret_cast<const float4*>(hp);
                *reinterpret_cast<float4*>(v + 4) = *reinterpret_cast<const float4*>(hp + 4);
                uint4 hi, lo;
                split8(v, hi, lo);
                unsigned off = toff(r, ch);
                *reinterpret_cast<uint4*>(smem + S_AHI + off) = hi;
                *reinterpret_cast<uint4*>(smem + S_ALO + off) = lo;
            }
        } else {
            const unsigned char* src = g_htile[(t - 1) & 1][bi];
#pragma unroll
            for (int c = tid; c < 4096; c += 512) {
                CP_ASYNC16(sbase + S_AHI + (unsigned)c * 16u, src + (size_t)c * 16);
            }
            asm volatile("cp.async.commit_group;");
        }

        // ---- gi + mask prefetch ----
        float gir[4], giz[4], gin[4];
        {
            const float* gib = g_gi + ((size_t)t * B_SZ + b) * G3 + jg;
            *reinterpret_cast<float4*>(gir) = __ldcs(reinterpret_cast<const float4*>(gib));
            *reinterpret_cast<float4*>(giz) = __ldcs(reinterpret_cast<const float4*>(gib + H_SZ));
            *reinterpret_cast<float4*>(gin) = __ldcs(reinterpret_cast<const float4*>(gib + 2 * H_SZ));
        }
        const float m = __ldg(masks + (size_t)t * B_SZ + b);

        if (t != 0) {
            asm volatile("cp.async.wait_group 0;" ::: "memory");
        }
        __syncthreads();

        // ---- tensor GEMM: this warp does 8 k-steps of its k-half ----
        float acc[6][4] = {};
#pragma unroll
        for (int ks = 0; ks < 8; ks++) {
            const int kc = (kh * 8 + ks) * 2;
            unsigned ahi[4], alo[4];
            unsigned aoffs = (unsigned)rowA * 512u + (unsigned)(((kc + parA) ^ (rowA & 7)) << 4);
            LDM4(ahi, sbase + S_AHI + aoffs);
            LDM4(alo, sbase + S_ALO + aoffs);
#pragma unroll
            for (int p = 0; p < 3; p++) {
                unsigned boffs = (unsigned)rowB[p] * 512u + (unsigned)(((kc + parB) ^ (rowB[p] & 7)) << 4);
                unsigned bh[4], bl[4];
                LDM4(bh, sbase + S_WHI + boffs);
                LDM4(bl, sbase + S_WLO + boffs);
                MMA16816(acc[2 * p],     ahi, bh[0], bh[1]);
                MMA16816(acc[2 * p + 1], ahi, bh[2], bh[3]);
                MMA16816(acc[2 * p],     ahi, bl[0], bl[1]);
                MMA16816(acc[2 * p + 1], ahi, bl[2], bl[3]);
                MMA16816(acc[2 * p],     alo, bh[0], bh[1]);
                MMA16816(acc[2 * p + 1], alo, bh[2], bh[3]);
            }
        }

        // ---- accumulators -> smem partials ----
        {
            const int r0 = wm * 16 + lane / 4;
            const int cb = wn * 48 + (lane % 4) * 2;
#pragma unroll
            for (int i = 0; i < 6; i++) {
                const int col = cb + (i >> 1) * 16 + (i & 1) * 8;
                *reinterpret_cast<float2*>(&sghk[r0 * GH_STR + col])       = make_float2(acc[i][0], acc[i][1]);
                *reinterpret_cast<float2*>(&sghk[(r0 + 8) * GH_STR + col]) = make_float2(acc[i][2], acc[i][3]);
            }
        }
        __syncthreads();

        // ---- gates (mask folded: gh_masked = m*gh_raw, hp = m*h_raw) ----
        {
            float4 r0 = *reinterpret_cast<const float4*>(&sgh[gr * GH_STR + jj0]);
            float4 r1 = *reinterpret_cast<const float4*>(&sgh[GH_HALF + gr * GH_STR + jj0]);
            float4 z0 = *reinterpret_cast<const float4*>(&sgh[gr * GH_STR + 32 + jj0]);
            float4 z1 = *reinterpret_cast<const float4*>(&sgh[GH_HALF + gr * GH_STR + 32 + jj0]);
            float4 n0 = *reinterpret_cast<const float4*>(&sgh[gr * GH_STR + 64 + jj0]);
            float4 n1 = *reinterpret_cast<const float4*>(&sgh[GH_HALF + gr * GH_STR + 64 + jj0]);
            float ghr[4] = {r0.x + r1.x, r0.y + r1.y, r0.z + r1.z, r0.w + r1.w};
            float ghz[4] = {z0.x + z1.x, z0.y + z1.y, z0.z + z1.z, z0.w + z1.w};
            float ghn[4] = {n0.x + n1.x, n0.y + n1.y, n0.z + n1.z, n0.w + n1.w};

            float hpv[4];
            {
                uint2 hi = *reinterpret_cast<const uint2*>(smem + S_AHI + hpo);
                uint2 lo = *reinterpret_cast<const uint2*>(smem + S_ALO + hpo);
                unpack2(hi.x, lo.x, hpv[0], hpv[1]);
                unpack2(hi.y, lo.y, hpv[2], hpv[3]);
            }

            float hv[4];
#pragma unroll
            for (int i = 0; i < 4; i++) {
                float br = sbias[jj0 + i];
                float bz = sbias[32 + jj0 + i];
                float bn = sbias[64 + jj0 + i];
                float r = fast_sigmoid(gir[i] + m * ghr[i] + br);
                float z = fast_sigmoid(giz[i] + m * ghz[i] + bz);
                float n = fast_tanh(gin[i] + r * (m * ghn[i] + bn));
                hv[i] = (1.0f - z) * n + z * (m * hpv[i]);
            }

            // h exchange write: split, already-swizzled tile image
            uint2 oh, ol;
            split4(hv, oh, ol);
            unsigned char* dst = g_htile[t & 1][bi];
            *reinterpret_cast<uint2*>(dst + hpo)         = oh;
            *reinterpret_cast<uint2*>(dst + 32768 + hpo) = ol;

            if (t == T_STEPS - 1) {
                float* fp = out + (size_t)T_STEPS * B_SZ * H_SZ + (size_t)b * H_SZ + jg;
                *reinterpret_cast<float4*>(fp) = make_float4(hv[0], hv[1], hv[2], hv[3]);
            }
        }

        // ---- release this CTA's flag as soon as h writes are visible ----
        __syncthreads();
        const unsigned target = bar_base + (unsigned)t + 1u;
        if (tid == 0) {
            asm volatile("st.release.gpu.global.u32 [%0], %1;"
                         :: "l"(&g_flags[bi][ji]), "r"(target) : "memory");
        }

        // ---- fused LN of y(t-1) = A tile rows (hides peer skew) ----
        if (t > 0 && w < 8) {
            uint4 hi = *reinterpret_cast<const uint4*>(smem + S_AHI + lnoff);
            uint4 lo = *reinterpret_cast<const uint4*>(smem + S_ALO + lnoff);
            float v[8];
            unpack2(hi.x, lo.x, v[0], v[1]);
            unpack2(hi.y, lo.y, v[2], v[3]);
            unpack2(hi.z, lo.z, v[4], v[5]);
            unpack2(hi.w, lo.w, v[6], v[7]);
            float s = v[0] + v[1] + v[2] + v[3] + v[4] + v[5] + v[6] + v[7];
#pragma unroll
            for (int o = 16; o; o >>= 1) s += __shfl_xor_sync(0xffffffffu, s, o);
            const float mu = s * (1.0f / 256.0f);
            float q = 0.f;
#pragma unroll
            for (int i = 0; i < 8; i++) { float d = v[i] - mu; q += d * d; }
#pragma unroll
            for (int o = 16; o; o >>= 1) q += __shfl_xor_sync(0xffffffffu, q, o);
            const float rs = rsqrtf(q * (1.0f / 256.0f) + 1e-5f);
            float o8[8];
#pragma unroll
            for (int i = 0; i < 8; i++) o8[i] = (v[i] - mu) * rs * lnw8[i] + lnb8[i];
            float* yp = out + ((size_t)(t - 1) * B_SZ + b0 + lrow) * H_SZ + lane * 8;
            *reinterpret_cast<float4*>(yp)     = *reinterpret_cast<float4*>(o8);
            *reinterpret_cast<float4*>(yp + 4) = *reinterpret_cast<float4*>(o8 + 4);
        }

        // ---- poll all 8 group flags ----
        if (tid == 0) {
            const unsigned* fb = &g_flags[bi][0];
            uint4 f0, f1;
            for (;;) {
                LDV4_VOL(f0, fb);
                LDV4_VOL(f1, fb + 4);
                if (f0.x == target && f0.y == target && f0.z == target && f0.w == target &&
                    f1.x == target && f1.y == target && f1.z == target && f1.w == target)
                    break;
            }
            asm volatile("fence.acq_rel.gpu;" ::: "memory");
        }
        __syncthreads();
    }

    // ---- epilogue: LN of y(T-1) from the final h tile ----
    {
        const unsigned char* src = g_htile[(T_STEPS - 1) & 1][bi];
#pragma unroll
        for (int c = tid; c < 4096; c += 512) {
            CP_ASYNC16(sbase + S_AHI + (unsigned)c * 16u, src + (size_t)c * 16);
        }
        asm volatile("cp.async.commit_group;");
        asm volatile("cp.async.wait_group 0;" ::: "memory");
        __syncthreads();

        if (w < 8) {
            uint4 hi = *reinterpret_cast<const uint4*>(smem + S_AHI + lnoff);
            uint4 lo = *reinterpret_cast<const uint4*>(smem + S_ALO + lnoff);
            float v[8];
            unpack2(hi.x, lo.x, v[0], v[1]);
            unpack2(hi.y, lo.y, v[2], v[3]);
            unpack2(hi.z, lo.z, v[4], v[5]);
            unpack2(hi.w, lo.w, v[6], v[7]);
            float s = v[0] + v[1] + v[2] + v[3] + v[4] + v[5] + v[6] + v[7];
#pragma unroll
            for (int o = 16; o; o >>= 1) s += __shfl_xor_sync(0xffffffffu, s, o);
            const float mu = s * (1.0f / 256.0f);
            float q = 0.f;
#pragma unroll
            for (int i = 0; i < 8; i++) { float d = v[i] - mu; q += d * d; }
#pragma unroll
            for (int o = 16; o; o >>= 1) q += __shfl_xor_sync(0xffffffffu, q, o);
            const float rs = rsqrtf(q * (1.0f / 256.0f) + 1e-5f);
            float o8[8];
#pragma unroll
            for (int i = 0; i < 8; i++) o8[i] = (v[i] - mu) * rs * lnw8[i] + lnb8[i];
            float* yp = out + ((size_t)(T_STEPS - 1) * B_SZ + b0 + lrow) * H_SZ + lane * 8;
            *reinterpret_cast<float4*>(yp)     = *reinterpret_cast<float4*>(o8);
            *reinterpret_cast<float4*>(yp + 4) = *reinterpret_cast<float4*>(o8 + 4);
        }
    }
}

// ---------------------------------------------------------------------------
extern "C" void kernel_launch(void* const* d_in, const int* in_sizes, int n_in,
                              void* d_out, int out_size)
{
    const float* x     = (const float*)d_in[0];
    const float* h0    = (const float*)d_in[1];
    const float* masks = (const float*)d_in[2];
    const float* W_ih  = (const float*)d_in[3];
    const float* W_hh  = (const float*)d_in[4];
    const float* b_ih  = (const float*)d_in[5];
    const float* b_hh  = (const float*)d_in[6];
    const float* ln_w  = (const float*)d_in[7];
    const float* ln_b  = (const float*)d_in[8];
    float* out = (float*)d_out;

    (void)in_sizes; (void)n_in; (void)out_size;

    cudaFuncSetAttribute(gi_mma, cudaFuncAttributeMaxDynamicSharedMemorySize, GI_SMEM);
    cudaFuncSetAttribute(gru_scan_mma, cudaFuncAttributeMaxDynamicSharedMemorySize, SMEM_SCAN);

    prep_wih<<<48, 256>>>(W_ih);

    gi_mma<<<(T_STEPS * B_SZ) / 128, 256, GI_SMEM>>>(x, b_ih);

    gru_scan_mma<<<SC_GRID, 512, SMEM_SCAN>>>(h0, masks, W_hh, b_hh, ln_w, ln_b, out);
}